// round 13
// baseline (speedup 1.0000x reference)
#include <cuda_runtime.h>

#define SEQ   512
#define BATCH 2048
#define IND   4
#define H     50
#define NTHR  640                // 20 warps
#define HP    56                 // floats per h row: 50 h + 4 x + 2 pad = 28 pairs
#define NBLK  147                // 146 CTAs x BT=14  +  1 CTA x BT=4  (one 148-SM wave)
#define MAINBT 14

typedef unsigned long long ull;

// ---- packed dual-fp32 (sm_103a FFMA2 path, PTX-only) ----
__device__ __forceinline__ ull pack2(float lo, float hi) {
    ull r; asm("mov.b64 %0, {%1, %2};" : "=l"(r) : "f"(lo), "f"(hi)); return r;
}
__device__ __forceinline__ void unpack2(ull v, float& lo, float& hi) {
    asm("mov.b64 {%0, %1}, %2;" : "=f"(lo), "=f"(hi) : "l"(v));
}
__device__ __forceinline__ void fma2(ull& d, ull a, ull b) {
    asm("fma.rn.f32x2 %0, %1, %2, %0;" : "+l"(d) : "l"(a), "l"(b));
}
__device__ __forceinline__ ull add2(ull a, ull b) {
    ull r; asm("add.rn.f32x2 %0, %1, %2;" : "=l"(r) : "l"(a), "l"(b)); return r;
}
__device__ __forceinline__ float hsum(ull v) {
    float lo, hi; unpack2(v, lo, hi); return lo + hi;
}

// ---- fast activations (known-good: final rel_err ~1.5e-7) ----
__device__ __forceinline__ float sigf(float x) {
    return __fdividef(1.0f, 1.0f + __expf(-x));
}
__device__ __forceinline__ float tanh_fast(float x) {
    float ax = fabsf(x);
    float e  = __expf(-2.0f * ax);
    float t  = __fdividef(1.0f - e, 1.0f + e);
    return copysignf(t, x);
}

// GHALF: offset of the hi-half partial buffer; padded so GHALF % 16 == 8
// (keeps the two k-half STS.64 streams on disjoint bank-pair phases).
constexpr int ghalf_of(int gs2) {
    return 100 * gs2 + ((8 - 100 * gs2) & 15);
}

template<int BT>
struct __align__(16) Smem {
    static constexpr int GS2 = BT + 1;            // pair-row stride (conflict-free pad)
    static constexpr int GH  = ghalf_of(GS2);
    float h1s [BT][HP];      // layer1 h (+ x in slots 50..53, pads zero)
    float h1rs[BT][HP];      // relu(h1)
    float h2s [BT][HP];      // layer2 h
    float h2rs[BT][HP];      // relu(h2)
    ull   gp1 [2 * GH];      // L1 gates: entry r = pair(row r, row r+100); lo/hi k-half
    ull   gp2a[2 * GH];      // L2 w_ih2 part
    ull   gp2b[2 * GH];      // L2 w_hh2 part
    float xs[BT][IND];       // staged x(t+1)
    float wfcs[52];
    float bfcs;
};

// cells: unit u in [0,50). Pair entry u holds gates (i_u, g_u); entry u+50 holds (f_u, o_u).
template<int BT>
__device__ __forceinline__ void l1_cell(Smem<BT>* S, int u, int b, float& c) {
    constexpr int GS2 = Smem<BT>::GS2, GH = Smem<BT>::GH;
    ull ig = add2(S->gp1[      u  * GS2 + b], S->gp1[GH +       u  * GS2 + b]);
    ull fo = add2(S->gp1[(u + 50) * GS2 + b], S->gp1[GH + (u + 50) * GS2 + b]);
    float gi, gg, gf, go;
    unpack2(ig, gi, gg);
    unpack2(fo, gf, go);
    float cn = sigf(gf) * c + sigf(gi) * tanh_fast(gg);
    c = cn;
    float hv = sigf(go) * tanh_fast(cn);
    S->h1s[b][u]  = hv;
    S->h1rs[b][u] = fmaxf(hv, 0.f);
}

template<int BT>
__device__ __forceinline__ void l2_cell(Smem<BT>* S, int u, int b, float& c) {
    constexpr int GS2 = Smem<BT>::GS2, GH = Smem<BT>::GH;
    ull ig = add2(add2(S->gp2a[      u  * GS2 + b], S->gp2a[GH +       u  * GS2 + b]),
                  add2(S->gp2b[      u  * GS2 + b], S->gp2b[GH +       u  * GS2 + b]));
    ull fo = add2(add2(S->gp2a[(u + 50) * GS2 + b], S->gp2a[GH + (u + 50) * GS2 + b]),
                  add2(S->gp2b[(u + 50) * GS2 + b], S->gp2b[GH + (u + 50) * GS2 + b]));
    float gi, gg, gf, go;
    unpack2(ig, gi, gg);
    unpack2(fo, gf, go);
    float cn = sigf(gf) * c + sigf(gi) * tanh_fast(gg);
    c = cn;
    float hv = sigf(go) * tanh_fast(cn);
    S->h2s[b][u]  = hv;
    S->h2rs[b][u] = fmaxf(hv, 0.f);
}

template<int BT>
__device__ __forceinline__ void run_lstm(
    char* smem_raw, int B0,
    const float* __restrict__ x,
    const float* __restrict__ w_ih1, const float* __restrict__ w_hh1,
    const float* __restrict__ b_ih1, const float* __restrict__ b_hh1,
    const float* __restrict__ w_ih2, const float* __restrict__ w_hh2,
    const float* __restrict__ b_ih2, const float* __restrict__ b_hh2,
    const float* __restrict__ w_fc,  const float* __restrict__ b_fc,
    float* __restrict__ out)
{
    Smem<BT>* S = (Smem<BT>*)smem_raw;
    constexpr int GS2 = Smem<BT>::GS2, GH = Smem<BT>::GH;
    constexpr int N1  = H * BT;                    // cells per layer

    const int tid = threadIdx.x;

    // ---- init: zero h arrays (incl pads) ----
    for (int i = tid; i < 4 * BT * HP; i += NTHR)
        ((float*)S->h1s)[i] = 0.f;
    if (tid < 52)  S->wfcs[tid] = (tid < H) ? w_fc[tid] : 0.f;
    if (tid == 0)  S->bfcs = b_fc[0];
    __syncthreads();
    if (tid < BT * IND) {                          // x(0) into h1 row slots
        int b = tid >> 2, d = tid & 3;
        S->h1s[b][H + d] = x[(B0 + b) * IND + d];
    }

    // ---- per-thread packed weights: 2 rows x half-k ----
    // Warp-uniform half mapping: within each 200-thread band,
    //   half = (u >= 100), r = u - 100*half.
    // All 32 lanes of a non-straddling warp share the same k-half ->
    // every LDS.128 broadcast touches ONE 16B line instead of two.
    ull w2a[14], w2b[14];
#pragma unroll
    for (int q = 0; q < 14; q++) { w2a[q] = 0ULL; w2b[q] = 0ULL; }
    float br0 = 0.f, br1 = 0.f;
    const float* hb = &S->h1s[0][0];
    ull* gdst = S->gp1;
    int  hoff = 0;

    if (tid < 600) {
        const int band = tid / 200;
        const int u    = tid - band * 200;
        const int half = (u >= 100) ? 1 : 0;       // warp-uniform (was u&1)
        const int r    = u - 100 * half;           // pair index 0..99
        hoff = half * 28;
        const float* wsrc = (band == 0) ? w_hh1 : (band == 1) ? w_ih2 : w_hh2;
#pragma unroll
        for (int q = 0; q < 14; q++) {
            const int P = 14 * half + q;
            float alo = 0.f, ahi = 0.f, blo = 0.f, bhi = 0.f;
            if (P < 25) {
                alo = wsrc[(r      ) * H + 2 * P]; ahi = wsrc[(r      ) * H + 2 * P + 1];
                blo = wsrc[(r + 100) * H + 2 * P]; bhi = wsrc[(r + 100) * H + 2 * P + 1];
            } else if (P < 27 && band == 0) {
                const int d = (P - 25) * 2;
                alo = w_ih1[(r      ) * IND + d];  ahi = w_ih1[(r      ) * IND + d + 1];
                blo = w_ih1[(r + 100) * IND + d];  bhi = w_ih1[(r + 100) * IND + d + 1];
            }
            w2a[q] = pack2(alo, ahi);
            w2b[q] = pack2(blo, bhi);
        }
        if (half == 0) {
            if (band == 0) { br0 = b_ih1[r] + b_hh1[r]; br1 = b_ih1[r + 100] + b_hh1[r + 100]; }
            if (band == 1) { br0 = b_ih2[r] + b_hh2[r]; br1 = b_ih2[r + 100] + b_hh2[r + 100]; }
        }
        if      (band == 0) { hb = &S->h1s [0][0]; gdst = S->gp1  + half * GH + r * GS2; }
        else if (band == 1) { hb = &S->h1rs[0][0]; gdst = S->gp2a + half * GH + r * GS2; }
        else                { hb = &S->h2s [0][0]; gdst = S->gp2b + half * GH + r * GS2; }
    }

    float cst[3];
#pragma unroll
    for (int j = 0; j < 3; j++) cst[j] = 0.f;
    __syncthreads();

    // Pipeline: A(t): L1-gates(t) || L2-gates(t-1) || FC(t-2) || prefetch x(t+1)
    //           B(t): L1-cells(t) || L2-cells(t-1) || copy x(t+1) into h1 slots
    for (int t = 0; t <= SEQ + 1; ++t) {
        // ================= phase A =================
        if (tid < 600) {
            const bool l1band = (tid < 200);
            const bool act = l1band ? (t < SEQ) : (t >= 1 && t <= SEQ);
            if (act) {
#pragma unroll 4
                for (int b = 0; b < BT; b++) {
                    const ulonglong2* hp = (const ulonglong2*)(hb + b * HP + hoff);
                    ull a0 = 0ULL, a1 = 0ULL, c0 = 0ULL, c1 = 0ULL;
#pragma unroll
                    for (int q = 0; q < 7; q++) {  // 7 LDS.128, 1 line/warp (uniform half)
                        ulonglong2 hv = hp[q];
                        fma2(a0, w2a[2 * q],     hv.x);
                        fma2(a1, w2a[2 * q + 1], hv.y);
                        fma2(c0, w2b[2 * q],     hv.x);
                        fma2(c1, w2b[2 * q + 1], hv.y);
                    }
                    float p0 = hsum(add2(a0, a1)) + br0;   // row r
                    float p1 = hsum(add2(c0, c1)) + br1;   // row r+100
                    gdst[b] = pack2(p0, p1);               // STS.64, conflict-free
                }
            }
        } else if (tid >= 600 && tid < 600 + BT) {
            if (t >= 2) {                               // FC for step t-2
                const int b = tid - 600;
                float a0 = S->bfcs, a1 = 0.f, a2 = 0.f, a3 = 0.f;
#pragma unroll
                for (int q = 0; q < 13; q++) {
                    float4 wv = *(const float4*)&S->wfcs[4 * q];
                    float4 hv = *(const float4*)&S->h2rs[b][4 * q];
                    a0 += wv.x * hv.x; a1 += wv.y * hv.y;
                    a2 += wv.z * hv.z; a3 += wv.w * hv.w;
                }
                out[(t - 2) * BATCH + B0 + b] = (a0 + a1) + (a2 + a3);
            }
        } else if (tid >= 624 && tid < 632) {
            if (t + 1 < SEQ) {                          // prefetch x(t+1) -> xs
                const int i = tid - 624;                // 0..7
#pragma unroll
                for (int j = 0; j < 7; j++) {
                    int idx = i * 7 + j;
                    if (idx < IND * BT) {
                        int b = idx >> 2, d = idx & 3;
                        S->xs[b][d] = x[((t + 1) * BATCH + B0 + b) * IND + d];
                    }
                }
            }
        }
        __syncthreads();

        // ================= phase B =================
        // cells c = tid + j*NTHR : c<N1 -> L1(t), unit u=c/BT ; N1<=c<2*N1 -> L2(t-1)
#pragma unroll
        for (int j = 0; j < 3; j++) {
            const int c = tid + j * NTHR;
            if (c < N1) {
                if (t < SEQ) l1_cell<BT>(S, c / BT, c % BT, cst[j]);
            } else if (c < 2 * N1) {
                if (t >= 1 && t <= SEQ) {
                    const int r = c - N1;
                    l2_cell<BT>(S, r / BT, r % BT, cst[j]);
                }
            }
        }
        if (tid >= 320 && tid < 320 + IND * BT) {       // x(t+1) into h1 slots
            if (t + 1 < SEQ) {
                int i2 = tid - 320;
                int b = i2 >> 2, d = i2 & 3;
                S->h1s[b][H + d] = S->xs[b][d];
            }
        }
        __syncthreads();
    }
}

__global__ __launch_bounds__(NTHR, 1)
void lstm_fused_kernel(
    const float* __restrict__ x,
    const float* __restrict__ w_ih1, const float* __restrict__ w_hh1,
    const float* __restrict__ b_ih1, const float* __restrict__ b_hh1,
    const float* __restrict__ w_ih2, const float* __restrict__ w_hh2,
    const float* __restrict__ b_ih2, const float* __restrict__ b_hh2,
    const float* __restrict__ w_fc,  const float* __restrict__ b_fc,
    float* __restrict__ out)
{
    extern __shared__ char smem_raw[];
    if (blockIdx.x < NBLK - 1) {
        run_lstm<MAINBT>(smem_raw, blockIdx.x * MAINBT,
                         x, w_ih1, w_hh1, b_ih1, b_hh1,
                         w_ih2, w_hh2, b_ih2, b_hh2, w_fc, b_fc, out);
    } else {
        run_lstm<4>(smem_raw, (NBLK - 1) * MAINBT,   // 146*14 = 2044, last 4 batches
                    x, w_ih1, w_hh1, b_ih1, b_hh1,
                    w_ih2, w_hh2, b_ih2, b_hh2, w_fc, b_fc, out);
    }
}

extern "C" void kernel_launch(void* const* d_in, const int* in_sizes, int n_in,
                              void* d_out, int out_size)
{
    const float* x     = (const float*)d_in[0];
    const float* w_ih1 = (const float*)d_in[1];
    const float* w_hh1 = (const float*)d_in[2];
    const float* b_ih1 = (const float*)d_in[3];
    const float* b_hh1 = (const float*)d_in[4];
    const float* w_ih2 = (const float*)d_in[5];
    const float* w_hh2 = (const float*)d_in[6];
    const float* b_ih2 = (const float*)d_in[7];
    const float* b_hh2 = (const float*)d_in[8];
    const float* w_fc  = (const float*)d_in[9];
    const float* b_fc  = (const float*)d_in[10];
    float* out = (float*)d_out;

    const int smem = (int)sizeof(Smem<MAINBT>);
    cudaFuncSetAttribute(lstm_fused_kernel,
                         cudaFuncAttributeMaxDynamicSharedMemorySize, smem);
    lstm_fused_kernel<<<NBLK, NTHR, smem>>>(
        x, w_ih1, w_hh1, b_ih1, b_hh1,
        w_ih2, w_hh2, b_ih2, b_hh2, w_fc, b_fc, out);
}

// round 14
// speedup vs baseline: 1.6679x; 1.6679x over previous
#include <cuda_runtime.h>

#define SEQ   512
#define BATCH 2048
#define IND   4
#define H     50
#define NTHR  640                // 20 warps
#define HP    56                 // floats per h row: 50 h + 4 x + 2 pad = 28 pairs
#define NBLK  147                // 146 CTAs x 14  +  1 CTA x 4 (guarded) = 2048 batches
#define BT    14                 // single instantiation; runt CTA guards I/O via bmax

typedef unsigned long long ull;

// ---- packed dual-fp32 (sm_103a FFMA2 path, PTX-only) ----
__device__ __forceinline__ ull pack2(float lo, float hi) {
    ull r; asm("mov.b64 %0, {%1, %2};" : "=l"(r) : "f"(lo), "f"(hi)); return r;
}
__device__ __forceinline__ void unpack2(ull v, float& lo, float& hi) {
    asm("mov.b64 {%0, %1}, %2;" : "=f"(lo), "=f"(hi) : "l"(v));
}
__device__ __forceinline__ void fma2(ull& d, ull a, ull b) {
    asm("fma.rn.f32x2 %0, %1, %2, %0;" : "+l"(d) : "l"(a), "l"(b));
}
__device__ __forceinline__ ull add2(ull a, ull b) {
    ull r; asm("add.rn.f32x2 %0, %1, %2;" : "=l"(r) : "l"(a), "l"(b)); return r;
}
__device__ __forceinline__ float hsum(ull v) {
    float lo, hi; unpack2(v, lo, hi); return lo + hi;
}

// ---- fast activations (known-good: final rel_err ~1.5e-7) ----
__device__ __forceinline__ float sigf(float x) {
    return __fdividef(1.0f, 1.0f + __expf(-x));
}
__device__ __forceinline__ float tanh_fast(float x) {
    float ax = fabsf(x);
    float e  = __expf(-2.0f * ax);
    float t  = __fdividef(1.0f - e, 1.0f + e);
    return copysignf(t, x);
}

// GHALF: offset of the hi-half partial buffer; padded so GHALF % 16 == 8
// (keeps the two k-half STS.64 streams on disjoint bank-pair phases).
#define GS2 (BT + 1)             // pair-row stride in ull (conflict-free pad)
#define GH  (100 * GS2 + ((8 - 100 * GS2) & 15))
#define N1  (H * BT)             // cells per layer

struct __align__(16) Smem {
    float h1s [BT][HP];      // layer1 h (+ x in slots 50..53, pads zero)
    float h1rs[BT][HP];      // relu(h1)
    float h2s [BT][HP];      // layer2 h
    float h2rs[BT][HP];      // relu(h2)
    ull   gp1 [2 * GH];      // L1 gates: entry r = pair(row r, row r+100); lo/hi k-half
    ull   gp2a[2 * GH];      // L2 w_ih2 part
    ull   gp2b[2 * GH];      // L2 w_hh2 part
    float xs[BT][IND];       // staged x(t+1)
    float wfcs[52];
    float bfcs;
};

// cells: unit u in [0,50). Pair entry u holds gates (i_u, g_u); entry u+50 holds (f_u, o_u).
__device__ __forceinline__ void l1_cell(Smem* S, int u, int b, float& c) {
    ull ig = add2(S->gp1[      u  * GS2 + b], S->gp1[GH +       u  * GS2 + b]);
    ull fo = add2(S->gp1[(u + 50) * GS2 + b], S->gp1[GH + (u + 50) * GS2 + b]);
    float gi, gg, gf, go;
    unpack2(ig, gi, gg);
    unpack2(fo, gf, go);
    float cn = sigf(gf) * c + sigf(gi) * tanh_fast(gg);
    c = cn;
    float hv = sigf(go) * tanh_fast(cn);
    S->h1s[b][u]  = hv;
    S->h1rs[b][u] = fmaxf(hv, 0.f);
}

__device__ __forceinline__ void l2_cell(Smem* S, int u, int b, float& c) {
    ull ig = add2(add2(S->gp2a[      u  * GS2 + b], S->gp2a[GH +       u  * GS2 + b]),
                  add2(S->gp2b[      u  * GS2 + b], S->gp2b[GH +       u  * GS2 + b]));
    ull fo = add2(add2(S->gp2a[(u + 50) * GS2 + b], S->gp2a[GH + (u + 50) * GS2 + b]),
                  add2(S->gp2b[(u + 50) * GS2 + b], S->gp2b[GH + (u + 50) * GS2 + b]));
    float gi, gg, gf, go;
    unpack2(ig, gi, gg);
    unpack2(fo, gf, go);
    float cn = sigf(gf) * c + sigf(gi) * tanh_fast(gg);
    c = cn;
    float hv = sigf(go) * tanh_fast(cn);
    S->h2s[b][u]  = hv;
    S->h2rs[b][u] = fmaxf(hv, 0.f);
}

__global__ __launch_bounds__(NTHR, 1)
void lstm_fused_kernel(
    const float* __restrict__ x,
    const float* __restrict__ w_ih1, const float* __restrict__ w_hh1,
    const float* __restrict__ b_ih1, const float* __restrict__ b_hh1,
    const float* __restrict__ w_ih2, const float* __restrict__ w_hh2,
    const float* __restrict__ b_ih2, const float* __restrict__ b_hh2,
    const float* __restrict__ w_fc,  const float* __restrict__ b_fc,
    float* __restrict__ out)
{
    extern __shared__ char smem_raw[];
    Smem* S = (Smem*)smem_raw;

    const int tid  = threadIdx.x;
    const int B0   = blockIdx.x * BT;
    const int bmax = min(BT, BATCH - B0);          // runt CTA: only 4 real batches

    // ---- init: zero h arrays (incl pads) ----
    for (int i = tid; i < 4 * BT * HP; i += NTHR)
        ((float*)S->h1s)[i] = 0.f;
    if (tid < 52)  S->wfcs[tid] = (tid < H) ? w_fc[tid] : 0.f;
    if (tid == 0)  S->bfcs = b_fc[0];
    __syncthreads();
    if (tid < BT * IND) {                          // x(0) into h1 row slots
        int b = tid >> 2, d = tid & 3;
        if (b < bmax) S->h1s[b][H + d] = x[(B0 + b) * IND + d];
    }

    // ---- per-thread packed weights: 2 rows x half-k (R12-proven mapping) ----
    ull w2a[14], w2b[14];
#pragma unroll
    for (int q = 0; q < 14; q++) { w2a[q] = 0ULL; w2b[q] = 0ULL; }
    float br0 = 0.f, br1 = 0.f;
    const float* hb = &S->h1s[0][0];
    ull* gdst = S->gp1;
    int  hoff = 0;

    if (tid < 600) {
        const int band = tid / 200;
        const int u    = tid - band * 200;
        const int half = u & 1;                    // R12 mapping (do NOT change)
        const int r    = u >> 1;                   // pair index 0..99
        hoff = half * 28;
        const float* wsrc = (band == 0) ? w_hh1 : (band == 1) ? w_ih2 : w_hh2;
#pragma unroll
        for (int q = 0; q < 14; q++) {
            const int P = 14 * half + q;
            float alo = 0.f, ahi = 0.f, blo = 0.f, bhi = 0.f;
            if (P < 25) {
                alo = wsrc[(r      ) * H + 2 * P]; ahi = wsrc[(r      ) * H + 2 * P + 1];
                blo = wsrc[(r + 100) * H + 2 * P]; bhi = wsrc[(r + 100) * H + 2 * P + 1];
            } else if (P < 27 && band == 0) {
                const int d = (P - 25) * 2;
                alo = w_ih1[(r      ) * IND + d];  ahi = w_ih1[(r      ) * IND + d + 1];
                blo = w_ih1[(r + 100) * IND + d];  bhi = w_ih1[(r + 100) * IND + d + 1];
            }
            w2a[q] = pack2(alo, ahi);
            w2b[q] = pack2(blo, bhi);
        }
        if (half == 0) {
            if (band == 0) { br0 = b_ih1[r] + b_hh1[r]; br1 = b_ih1[r + 100] + b_hh1[r + 100]; }
            if (band == 1) { br0 = b_ih2[r] + b_hh2[r]; br1 = b_ih2[r + 100] + b_hh2[r + 100]; }
        }
        if      (band == 0) { hb = &S->h1s [0][0]; gdst = S->gp1  + half * GH + r * GS2; }
        else if (band == 1) { hb = &S->h1rs[0][0]; gdst = S->gp2a + half * GH + r * GS2; }
        else                { hb = &S->h2s [0][0]; gdst = S->gp2b + half * GH + r * GS2; }
    }

    float cst[3];
#pragma unroll
    for (int j = 0; j < 3; j++) cst[j] = 0.f;
    __syncthreads();

    // Pipeline: A(t): L1-gates(t) || L2-gates(t-1) || FC(t-2) || prefetch x(t+1)
    //           B(t): L1-cells(t) || L2-cells(t-1) || copy x(t+1) into h1 slots
    for (int t = 0; t <= SEQ + 1; ++t) {
        // ================= phase A =================
        if (tid < 600) {
            const bool l1band = (tid < 200);
            const bool act = l1band ? (t < SEQ) : (t >= 1 && t <= SEQ);
            if (act) {
#pragma unroll 2
                for (int b = 0; b < BT; b++) {
                    const ulonglong2* hp = (const ulonglong2*)(hb + b * HP + hoff);
                    ull a0 = 0ULL, a1 = 0ULL, c0 = 0ULL, c1 = 0ULL;
#pragma unroll
                    for (int q = 0; q < 7; q++) {  // 7 LDS.128 broadcast
                        ulonglong2 hv = hp[q];
                        fma2(a0, w2a[2 * q],     hv.x);
                        fma2(a1, w2a[2 * q + 1], hv.y);
                        fma2(c0, w2b[2 * q],     hv.x);
                        fma2(c1, w2b[2 * q + 1], hv.y);
                    }
                    float p0 = hsum(add2(a0, a1)) + br0;   // row r
                    float p1 = hsum(add2(c0, c1)) + br1;   // row r+100
                    gdst[b] = pack2(p0, p1);               // STS.64, conflict-free
                }
            }
        } else if (tid >= 600 && tid < 600 + BT) {
            if (t >= 2) {                               // FC for step t-2
                const int b = tid - 600;
                if (b < bmax) {
                    float a0 = S->bfcs, a1 = 0.f, a2 = 0.f, a3 = 0.f;
#pragma unroll
                    for (int q = 0; q < 13; q++) {
                        float4 wv = *(const float4*)&S->wfcs[4 * q];
                        float4 hv = *(const float4*)&S->h2rs[b][4 * q];
                        a0 += wv.x * hv.x; a1 += wv.y * hv.y;
                        a2 += wv.z * hv.z; a3 += wv.w * hv.w;
                    }
                    out[(t - 2) * BATCH + B0 + b] = (a0 + a1) + (a2 + a3);
                }
            }
        } else if (tid >= 624 && tid < 632) {
            if (t + 1 < SEQ) {                          // prefetch x(t+1) -> xs
                const int i = tid - 624;                // 0..7
#pragma unroll
                for (int j = 0; j < 7; j++) {
                    int idx = i * 7 + j;
                    if (idx < IND * BT) {
                        int b = idx >> 2, d = idx & 3;
                        if (b < bmax)
                            S->xs[b][d] = x[((t + 1) * BATCH + B0 + b) * IND + d];
                    }
                }
            }
        }
        __syncthreads();

        // ================= phase B =================
        // cells c = tid + j*NTHR : c<N1 -> L1(t), unit u=c/BT ; N1<=c<2*N1 -> L2(t-1)
#pragma unroll
        for (int j = 0; j < 3; j++) {
            const int c = tid + j * NTHR;
            if (c < N1) {
                if (t < SEQ) l1_cell(S, c / BT, c % BT, cst[j]);
            } else if (c < 2 * N1) {
                if (t >= 1 && t <= SEQ) {
                    const int r = c - N1;
                    l2_cell(S, r / BT, r % BT, cst[j]);
                }
            }
        }
        if (tid >= 320 && tid < 320 + IND * BT) {       // x(t+1) into h1 slots
            if (t + 1 < SEQ) {
                int i2 = tid - 320;
                int b = i2 >> 2, d = i2 & 3;
                if (b < bmax) S->h1s[b][H + d] = S->xs[b][d];
            }
        }
        __syncthreads();
    }
}

extern "C" void kernel_launch(void* const* d_in, const int* in_sizes, int n_in,
                              void* d_out, int out_size)
{
    const float* x     = (const float*)d_in[0];
    const float* w_ih1 = (const float*)d_in[1];
    const float* w_hh1 = (const float*)d_in[2];
    const float* b_ih1 = (const float*)d_in[3];
    const float* b_hh1 = (const float*)d_in[4];
    const float* w_ih2 = (const float*)d_in[5];
    const float* w_hh2 = (const float*)d_in[6];
    const float* b_ih2 = (const float*)d_in[7];
    const float* b_hh2 = (const float*)d_in[8];
    const float* w_fc  = (const float*)d_in[9];
    const float* b_fc  = (const float*)d_in[10];
    float* out = (float*)d_out;

    const int smem = (int)sizeof(Smem);
    cudaFuncSetAttribute(lstm_fused_kernel,
                         cudaFuncAttributeMaxDynamicSharedMemorySize, smem);
    lstm_fused_kernel<<<NBLK, NTHR, smem>>>(
        x, w_ih1, w_hh1, b_ih1, b_hh1,
        w_ih2, w_hh2, b_ih2, b_hh2, w_fc, b_fc, out);
}